// round 13
// baseline (speedup 1.0000x reference)
#include <cuda_runtime.h>
#include <cuda_bf16.h>
#include <stdint.h>
#include <math.h>

// Problem constants
#define BATCH 16
#define SEQ 512
#define DM 1024
#define NH 16
#define HD 64
#define NTOK (BATCH * SEQ)   // 8192

// ---------------- scratch (allocation-free: __device__ globals) ----------------
__device__ float g_q[NTOK * DM];          // fp32 Q proj (rope input)
__device__ float g_k[NTOK * DM];          // fp32 K proj (rope input)
__device__ __nv_bfloat16 g_wh[4u * DM * DM];
__device__ __nv_bfloat16 g_wl[4u * DM * DM];
__device__ __nv_bfloat16 g_ah[3u * NTOK * DM];
__device__ __nv_bfloat16 g_al[3u * NTOK * DM];
__device__ __nv_bfloat16 g_qh[NTOK * DM];
__device__ __nv_bfloat16 g_ql[NTOK * DM];
__device__ __nv_bfloat16 g_kh[NTOK * DM];
__device__ __nv_bfloat16 g_kl[NTOK * DM];
__device__ __nv_bfloat16 g_vh[NTOK * DM];
__device__ __nv_bfloat16 g_vl[NTOK * DM];
__device__ __nv_bfloat16 g_ctxh[NTOK * DM];
__device__ __nv_bfloat16 g_ctxl[NTOK * DM];

// ---------------- warp-level tensor core primitives ----------------------------
__device__ __forceinline__ uint32_t smem_u32(const void* p) {
    uint32_t a;
    asm("{ .reg .u64 t; cvta.to.shared.u64 t, %1; cvt.u32.u64 %0, t; }"
        : "=r"(a) : "l"(p));
    return a;
}
__device__ __forceinline__ void ldm_x4(uint32_t* r, uint32_t addr) {
    asm volatile("ldmatrix.sync.aligned.m8n8.x4.shared.b16 {%0,%1,%2,%3}, [%4];"
        : "=r"(r[0]), "=r"(r[1]), "=r"(r[2]), "=r"(r[3]) : "r"(addr));
}
__device__ __forceinline__ void ldm_x2(uint32_t* r, uint32_t addr) {
    asm volatile("ldmatrix.sync.aligned.m8n8.x2.shared.b16 {%0,%1}, [%2];"
        : "=r"(r[0]), "=r"(r[1]) : "r"(addr));
}
__device__ __forceinline__ void ldm_x2t(uint32_t* r, uint32_t addr) {
    asm volatile("ldmatrix.sync.aligned.m8n8.x2.trans.shared.b16 {%0,%1}, [%2];"
        : "=r"(r[0]), "=r"(r[1]) : "r"(addr));
}
__device__ __forceinline__ void mma_bf16(float* d, const uint32_t* a, const uint32_t* b) {
    asm volatile("mma.sync.aligned.m16n8k16.row.col.f32.bf16.bf16.f32 "
        "{%0,%1,%2,%3}, {%4,%5,%6,%7}, {%8,%9}, {%0,%1,%2,%3};"
        : "+f"(d[0]), "+f"(d[1]), "+f"(d[2]), "+f"(d[3])
        : "r"(a[0]), "r"(a[1]), "r"(a[2]), "r"(a[3]), "r"(b[0]), "r"(b[1]));
}
__device__ __forceinline__ void cp16(uint32_t dst, const void* src) {
    asm volatile("cp.async.cg.shared.global [%0], [%1], 16;" :: "r"(dst), "l"(src));
}
#define CP_COMMIT() asm volatile("cp.async.commit_group;" ::: "memory")
template <int N> __device__ __forceinline__ void cp_wait() {
    asm volatile("cp.async.wait_group %0;" :: "n"(N) : "memory");
}

// fast exp on the FMA/ALU pipes (no MUFU). |rel err| < 3e-6 for x <= 0.
__device__ __forceinline__ float fexp(float x) {
    float t = fmaxf(x * 1.4426950408889634f, -125.0f);
    const float magic = 12582912.0f;
    float z = t + magic;
    int   n = __float_as_int(z) - 0x4B400000;
    float f = t - (z - magic);
    float p = 0.00133336f;
    p = fmaf(p, f, 0.00961813f);
    p = fmaf(p, f, 0.05550411f);
    p = fmaf(p, f, 0.24022651f);
    p = fmaf(p, f, 0.69314718f);
    p = fmaf(p, f, 1.0f);
    return p * __int_as_float((n + 127) << 23);
}

// split helpers: hi = truncate-to-bf16(x), lo = truncate-to-bf16(x - hi)
__device__ __forceinline__ void split2_u32(float a, float b, uint32_t& hi, uint32_t& lo) {
    const uint32_t ua = __float_as_uint(a), ub = __float_as_uint(b);
    const uint32_t ra = __float_as_uint(a - __uint_as_float(ua & 0xFFFF0000u));
    const uint32_t rb = __float_as_uint(b - __uint_as_float(ub & 0xFFFF0000u));
    hi = __byte_perm(ua, ub, 0x7632);
    lo = __byte_perm(ra, rb, 0x7632);
}

// ---------------- pre-split kernels: fp32 -> bf16 hi/lo ------------------------
__device__ __forceinline__ void split4_store(
    const float* __restrict__ src, __nv_bfloat16* dh, __nv_bfloat16* dl, size_t i)
{
    const float4 v = *reinterpret_cast<const float4*>(src + i);
    uint32_t h0, l0, h1, l1;
    split2_u32(v.x, v.y, h0, l0);
    split2_u32(v.z, v.w, h1, l1);
    uint2 hi, lo;
    hi.x = h0; hi.y = h1; lo.x = l0; lo.y = l1;
    *reinterpret_cast<uint2*>(dh + i) = hi;
    *reinterpret_cast<uint2*>(dl + i) = lo;
}

__global__ __launch_bounds__(256) void split_w_all(
    const float* __restrict__ W0, const float* __restrict__ W1,
    const float* __restrict__ W2, const float* __restrict__ W3)
{
    const float* W = (blockIdx.y == 0) ? W0
                   : (blockIdx.y == 1) ? W1
                   : (blockIdx.y == 2) ? W2 : W3;
    const size_t d0 = (size_t)blockIdx.y * DM * DM;
    const size_t i = ((size_t)blockIdx.x * 256 + threadIdx.x) * 4;
    split4_store(W, g_wh + d0, g_wl + d0, i);
}

__global__ __launch_bounds__(256) void split_act(
    const float* __restrict__ A0, const float* __restrict__ A1,
    const float* __restrict__ A2)
{
    const float* A = (blockIdx.y == 0) ? A0
                   : (blockIdx.y == 1) ? A1 : A2;
    const size_t d0 = (size_t)blockIdx.y * NTOK * DM;
    const size_t i = ((size_t)blockIdx.x * 256 + threadIdx.x) * 4;
    split4_store(A, g_ah + d0, g_al + d0, i);
}

// ================== max-ILP mma.sync GEMM (1 CTA/SM, full-stage preload) =======
#define GST 40
#define SSB (128 * GST * 2)   // 10240 B per array per stage
#define GSMEM (8 * SSB)       // 81920 B

// mode 0: fused QKV (blockIdx.z = sel 0..2); mode 1: O projection (sel 3)
__global__ __launch_bounds__(256, 1) void gemm_mma(
    const float* __restrict__ b0, const float* __restrict__ b1,
    const float* __restrict__ b2, float* Cout, int mode)
{
    const int sel = (mode == 0) ? (int)blockIdx.z : 3;
    const __nv_bfloat16* ah = (sel < 3) ? g_ah + (size_t)sel * NTOK * DM : g_ctxh;
    const __nv_bfloat16* al = (sel < 3) ? g_al + (size_t)sel * NTOK * DM : g_ctxl;
    const __nv_bfloat16* wh = g_wh + (size_t)sel * DM * DM;
    const __nv_bfloat16* wl = g_wl + (size_t)sel * DM * DM;
    const float* bias = (sel == 0) ? b0 : (sel == 1) ? b1 : (sel == 2) ? b2 : b0;

    extern __shared__ __align__(16) __nv_bfloat16 smg[];
    const uint32_t smB = smem_u32(smg);

    const int tid = threadIdx.x;
    const int lane = tid & 31;
    const int wid = tid >> 5;
    const int wm = wid & 1;
    const int wn = wid >> 1;
    const int bm = blockIdx.y * 128;
    const int bn = blockIdx.x * 128;

    const int grow = tid >> 1;
    const int gcol = (tid & 1) * 16;
    const uint32_t rcB = (uint32_t)(grow * GST + gcol) * 2;
    const size_t aRow = (size_t)(bm + grow) * DM + gcol;
    const size_t bRow = (size_t)(bn + grow) * DM + gcol;

    const int la = lane & 15;
    const uint32_t aRowOff = (uint32_t)((wm * 64 + la) * GST + (lane >> 4) * 8) * 2;
    const uint32_t bRowOff = (uint32_t)((wn * 32 + (la & 7)) * GST + ((la >> 3) & 1) * 8) * 2;

    float acc[4][4][4];
    #pragma unroll
    for (int mt = 0; mt < 4; mt++)
        #pragma unroll
        for (int nt = 0; nt < 4; nt++)
            #pragma unroll
            for (int e = 0; e < 4; e++) acc[mt][nt][e] = 0.f;

    {
        const uint32_t d = smB + rcB;
        cp16(d,               ah + aRow); cp16(d + 16,           ah + aRow + 8);
        cp16(d + 2 * SSB,     al + aRow); cp16(d + 2 * SSB + 16, al + aRow + 8);
        cp16(d + 4 * SSB,     wh + bRow); cp16(d + 4 * SSB + 16, wh + bRow + 8);
        cp16(d + 6 * SSB,     wl + bRow); cp16(d + 6 * SSB + 16, wl + bRow + 8);
        CP_COMMIT();
    }

    #pragma unroll 1
    for (int it = 0; it < DM / 32; it++) {
        if (it + 1 < DM / 32) {
            const uint32_t d = smB + ((it + 1) & 1) * SSB + rcB;
            const size_t ao = aRow + (it + 1) * 32;
            const size_t bo = bRow + (it + 1) * 32;
            cp16(d,               ah + ao); cp16(d + 16,           ah + ao + 8);
            cp16(d + 2 * SSB,     al + ao); cp16(d + 2 * SSB + 16, al + ao + 8);
            cp16(d + 4 * SSB,     wh + bo); cp16(d + 4 * SSB + 16, wh + bo + 8);
            cp16(d + 6 * SSB,     wl + bo); cp16(d + 6 * SSB + 16, wl + bo + 8);
            CP_COMMIT();
            cp_wait<1>();
        } else {
            cp_wait<0>();
        }
        __syncthreads();

        const uint32_t sb = (uint32_t)((it & 1) * SSB);
        const uint32_t aHiB = smB + sb;
        const uint32_t aLoB = smB + 2 * SSB + sb;
        const uint32_t bHiB = smB + 4 * SSB + sb;
        const uint32_t bLoB = smB + 6 * SSB + sb;

        // preload ALL fragments for both kk halves of this stage
        uint32_t ahf[2][4][4], alf[2][4][4], bhf[2][4][2], blf[2][4][2];
        #pragma unroll
        for (int kk = 0; kk < 2; kk++) {
            const uint32_t kOff = (uint32_t)(kk * 16) * 2;
            #pragma unroll
            for (int mt = 0; mt < 4; mt++) {
                const uint32_t ro = aRowOff + (uint32_t)(mt * 16 * GST) * 2 + kOff;
                ldm_x4(ahf[kk][mt], aHiB + ro);
                ldm_x4(alf[kk][mt], aLoB + ro);
            }
            #pragma unroll
            for (int nt = 0; nt < 4; nt++) {
                const uint32_t ro = bRowOff + (uint32_t)(nt * 8 * GST) * 2 + kOff;
                ldm_x2(bhf[kk][nt], bHiB + ro);
                ldm_x2(blf[kk][nt], bLoB + ro);
            }
        }
        // 6 passes x 16 independent MMAs (chain gap 16-32)
        #pragma unroll
        for (int kk = 0; kk < 2; kk++)
            #pragma unroll
            for (int mt = 0; mt < 4; mt++)
                #pragma unroll
                for (int nt = 0; nt < 4; nt++)
                    mma_bf16(acc[mt][nt], ahf[kk][mt], bhf[kk][nt]);
        #pragma unroll
        for (int kk = 0; kk < 2; kk++)
            #pragma unroll
            for (int mt = 0; mt < 4; mt++)
                #pragma unroll
                for (int nt = 0; nt < 4; nt++)
                    mma_bf16(acc[mt][nt], ahf[kk][mt], blf[kk][nt]);
        #pragma unroll
        for (int kk = 0; kk < 2; kk++)
            #pragma unroll
            for (int mt = 0; mt < 4; mt++)
                #pragma unroll
                for (int nt = 0; nt < 4; nt++)
                    mma_bf16(acc[mt][nt], alf[kk][mt], bhf[kk][nt]);
        __syncthreads();
    }

    const int er = lane >> 2;
    const int ec = (lane & 3) * 2;
    if (sel == 2) {
        // V projection: write pre-split bf16 hi/lo
        #pragma unroll
        for (int mt = 0; mt < 4; mt++) {
            #pragma unroll
            for (int nt = 0; nt < 4; nt++) {
                const int col = bn + wn * 32 + nt * 8 + ec;
                const float c0 = bias[col], c1 = bias[col + 1];
                const int r0 = bm + wm * 64 + mt * 16 + er;
                uint32_t h, l;
                split2_u32(acc[mt][nt][0] + c0, acc[mt][nt][1] + c1, h, l);
                *reinterpret_cast<uint32_t*>(&g_vh[(size_t)r0 * DM + col]) = h;
                *reinterpret_cast<uint32_t*>(&g_vl[(size_t)r0 * DM + col]) = l;
                split2_u32(acc[mt][nt][2] + c0, acc[mt][nt][3] + c1, h, l);
                *reinterpret_cast<uint32_t*>(&g_vh[(size_t)(r0 + 8) * DM + col]) = h;
                *reinterpret_cast<uint32_t*>(&g_vl[(size_t)(r0 + 8) * DM + col]) = l;
            }
        }
    } else {
        float* C = (sel == 0) ? g_q : (sel == 1) ? g_k : Cout;
        #pragma unroll
        for (int mt = 0; mt < 4; mt++) {
            #pragma unroll
            for (int nt = 0; nt < 4; nt++) {
                const int col = bn + wn * 32 + nt * 8 + ec;
                const float c0 = bias[col], c1 = bias[col + 1];
                const int r0 = bm + wm * 64 + mt * 16 + er;
                float2 v0, v1;
                v0.x = acc[mt][nt][0] + c0; v0.y = acc[mt][nt][1] + c1;
                v1.x = acc[mt][nt][2] + c0; v1.y = acc[mt][nt][3] + c1;
                *reinterpret_cast<float2*>(&C[(size_t)r0 * DM + col]) = v0;
                *reinterpret_cast<float2*>(&C[(size_t)(r0 + 8) * DM + col]) = v1;
            }
        }
    }
}

// ---------------- RoPE + split: fp32 q,k -> roped bf16 hi/lo -------------------
__global__ __launch_bounds__(512) void rope_split()
{
    const int token = blockIdx.x;
    const int pos = token & (SEQ - 1);
    const int h = threadIdx.x >> 5;
    const int i = threadIdx.x & 31;

    const float expo = (float)(2 * i) / 64.0f;
    const float invf = 1.0f / powf(10000.0f, expo);
    const float ang = (float)pos * invf;
    const float c = cosf(ang);
    const float s = sinf(ang);

    const size_t base = (size_t)token * DM + h * HD;
    {
        const float a = g_q[base + i], b = g_q[base + i + 32];
        const float r1 = 0.125f * (a * c - b * s);
        const float r2 = 0.125f * (b * c + a * s);
        const uint32_t u1 = __float_as_uint(r1), u2 = __float_as_uint(r2);
        g_qh[base + i]      = __ushort_as_bfloat16((unsigned short)(u1 >> 16));
        g_qh[base + i + 32] = __ushort_as_bfloat16((unsigned short)(u2 >> 16));
        const float l1 = r1 - __uint_as_float(u1 & 0xFFFF0000u);
        const float l2 = r2 - __uint_as_float(u2 & 0xFFFF0000u);
        g_ql[base + i]      = __ushort_as_bfloat16((unsigned short)(__float_as_uint(l1) >> 16));
        g_ql[base + i + 32] = __ushort_as_bfloat16((unsigned short)(__float_as_uint(l2) >> 16));
    }
    {
        const float a = g_k[base + i], b = g_k[base + i + 32];
        const float r1 = a * c - b * s;
        const float r2 = b * c + a * s;
        const uint32_t u1 = __float_as_uint(r1), u2 = __float_as_uint(r2);
        g_kh[base + i]      = __ushort_as_bfloat16((unsigned short)(u1 >> 16));
        g_kh[base + i + 32] = __ushort_as_bfloat16((unsigned short)(u2 >> 16));
        const float l1 = r1 - __uint_as_float(u1 & 0xFFFF0000u);
        const float l2 = r2 - __uint_as_float(u2 & 0xFFFF0000u);
        g_kl[base + i]      = __ushort_as_bfloat16((unsigned short)(__float_as_uint(l1) >> 16));
        g_kl[base + i + 32] = __ushort_as_bfloat16((unsigned short)(__float_as_uint(l2) >> 16));
    }
}

// ================== mma.sync flash attention (bf16 cp.async inputs) ============
#define AST 72

__global__ __launch_bounds__(128) void attn_mma()
{
    __shared__ __align__(16) __nv_bfloat16 sKh[64 * AST];
    __shared__ __align__(16) __nv_bfloat16 sKl[64 * AST];
    __shared__ __align__(16) __nv_bfloat16 sVh[64 * AST];
    __shared__ __align__(16) __nv_bfloat16 sVl[64 * AST];

    const int tid = threadIdx.x;
    const int lane = tid & 31;
    const int w = tid >> 5;
    const int q0 = blockIdx.x * 64;
    const int h  = blockIdx.y;
    const int b  = blockIdx.z;

    const uint32_t kHiB = smem_u32(sKh), kLoB = smem_u32(sKl);
    const uint32_t vHiB = smem_u32(sVh), vLoB = smem_u32(sVl);

    // loader mapping: row = tid>>1, 32-elem half = tid&1; 4 cp16 per array
    const int lrow = tid >> 1;
    const int lhalf = tid & 1;
    const uint32_t sOff = (uint32_t)(lrow * AST + lhalf * 32) * 2;
    const size_t gColBase = (size_t)h * HD + lhalf * 32;

    // ---- stage Q (pre-roped, pre-scaled, pre-split) ----
    {
        const size_t src = (size_t)(b * SEQ + q0 + lrow) * DM + gColBase;
        #pragma unroll
        for (int cix = 0; cix < 4; cix++) {
            cp16(kHiB + sOff + cix * 16, g_qh + src + cix * 8);
            cp16(kLoB + sOff + cix * 16, g_ql + src + cix * 8);
        }
        CP_COMMIT();
        cp_wait<0>();
    }
    __syncthreads();

    uint32_t qh[4][4], ql[4][4];
    {
        const uint32_t ro0 = (uint32_t)((w * 16 + (lane & 15)) * AST + (lane >> 4) * 8) * 2;
        #pragma unroll
        for (int kc = 0; kc < 4; kc++) {
            ldm_x4(qh[kc], kHiB + ro0 + (uint32_t)(kc * 16) * 2);
            ldm_x4(ql[kc], kLoB + ro0 + (uint32_t)(kc * 16) * 2);
        }
    }
    __syncthreads();

    float o[8][4];
    #pragma unroll
    for (int nt = 0; nt < 8; nt++)
        #pragma unroll
        for (int e = 0; e < 4; e++) o[nt][e] = 0.f;
    float m0 = -3.0e38f, m1 = -3.0e38f, l0 = 0.f, l1 = 0.f;

    const uint32_t bro = (uint32_t)((lane & 7) * AST + ((lane >> 3) & 1) * 8) * 2;
    const uint32_t vro = (uint32_t)(((lane & 7) + 8 * ((lane >> 3) & 1)) * AST) * 2;

    #pragma unroll 1
    for (int kt = 0; kt < SEQ / 64; kt++) {
        // ---- load K/V tiles (pre-split bf16, cp.async; 4 cp16 per array) ----
        {
            const size_t src = (size_t)(b * SEQ + kt * 64 + lrow) * DM + gColBase;
            #pragma unroll
            for (int cix = 0; cix < 4; cix++) {
                cp16(kHiB + sOff + cix * 16, g_kh + src + cix * 8);
                cp16(kLoB + sOff + cix * 16, g_kl + src + cix * 8);
                cp16(vHiB + sOff + cix * 16, g_vh + src + cix * 8);
                cp16(vLoB + sOff + cix * 16, g_vl + src + cix * 8);
            }
            CP_COMMIT();
            cp_wait<0>();
        }
        __syncthreads();

        float s[8][4];
        #pragma unroll
        for (int nt = 0; nt < 8; nt++)
            #pragma unroll
            for (int e = 0; e < 4; e++) s[nt][e] = 0.f;

        #pragma unroll
        for (int kc = 0; kc < 4; kc++) {
            const uint32_t kOff = (uint32_t)(kc * 16) * 2;
            #pragma unroll
            for (int nt = 0; nt < 8; nt++) {
                const uint32_t ro = bro + (uint32_t)(nt * 8 * AST) * 2 + kOff;
                uint32_t bh[2], bl[2];
                ldm_x2(bh, kHiB + ro);
                ldm_x2(bl, kLoB + ro);
                mma_bf16(s[nt], qh[kc], bh);
                mma_bf16(s[nt], qh[kc], bl);
                mma_bf16(s[nt], ql[kc], bh);
            }
        }

        float tm0 = -3.0e38f, tm1 = -3.0e38f;
        #pragma unroll
        for (int nt = 0; nt < 8; nt++) {
            tm0 = fmaxf(tm0, fmaxf(s[nt][0], s[nt][1]));
            tm1 = fmaxf(tm1, fmaxf(s[nt][2], s[nt][3]));
        }
        #pragma unroll
        for (int off = 1; off < 4; off <<= 1) {
            tm0 = fmaxf(tm0, __shfl_xor_sync(0xffffffffu, tm0, off));
            tm1 = fmaxf(tm1, __shfl_xor_sync(0xffffffffu, tm1, off));
        }
        const float nm0 = fmaxf(m0, tm0), nm1 = fmaxf(m1, tm1);
        const float corr0 = fexp(m0 - nm0), corr1 = fexp(m1 - nm1);
        float rs0 = 0.f, rs1 = 0.f;
        #pragma unroll
        for (int nt = 0; nt < 8; nt++) {
            s[nt][0] = fexp(s[nt][0] - nm0);
            s[nt][1] = fexp(s[nt][1] - nm0);
            s[nt][2] = fexp(s[nt][2] - nm1);
            s[nt][3] = fexp(s[nt][3] - nm1);
            rs0 += s[nt][0] + s[nt][1];
            rs1 += s[nt][2] + s[nt][3];
        }
        #pragma unroll
        for (int off = 1; off < 4; off <<= 1) {
            rs0 += __shfl_xor_sync(0xffffffffu, rs0, off);
            rs1 += __shfl_xor_sync(0xffffffffu, rs1, off);
        }
        l0 = l0 * corr0 + rs0;  m0 = nm0;
        l1 = l1 * corr1 + rs1;  m1 = nm1;
        #pragma unroll
        for (int nt = 0; nt < 8; nt++) {
            o[nt][0] *= corr0; o[nt][1] *= corr0;
            o[nt][2] *= corr1; o[nt][3] *= corr1;
        }

        uint32_t ph[4][4], pl[4][4];
        #pragma unroll
        for (int j = 0; j < 4; j++) {
            const int ta = 2 * j, tb = 2 * j + 1;
            split2_u32(s[ta][0], s[ta][1], ph[j][0], pl[j][0]);
            split2_u32(s[ta][2], s[ta][3], ph[j][1], pl[j][1]);
            split2_u32(s[tb][0], s[tb][1], ph[j][2], pl[j][2]);
            split2_u32(s[tb][2], s[tb][3], ph[j][3], pl[j][3]);
        }

        #pragma unroll
        for (int j = 0; j < 4; j++) {
            const uint32_t jOff = (uint32_t)(j * 16 * AST) * 2;
            #pragma unroll
            for (int nt = 0; nt < 8; nt++) {
                const uint32_t ro = vro + jOff + (uint32_t)(nt * 8) * 2;
                uint32_t bh[2], bl[2];
                ldm_x2t(bh, vHiB + ro);
                ldm_x2t(bl, vLoB + ro);
                mma_bf16(o[nt], ph[j], bh);
                mma_bf16(o[nt], ph[j], bl);
                mma_bf16(o[nt], pl[j], bh);
            }
        }
        __syncthreads();
    }

    const float i0 = 1.0f / l0, i1 = 1.0f / l1;
    const int er = lane >> 2;
    const int ec = (lane & 3) * 2;
    #pragma unroll
    for (int nt = 0; nt < 8; nt++) {
        const int col = h * HD + nt * 8 + ec;
        const size_t r0 = (size_t)(b * SEQ + q0 + w * 16 + er) * DM + col;
        const size_t r1 = r0 + 8 * DM;
        uint32_t hh, ll;
        split2_u32(o[nt][0] * i0, o[nt][1] * i0, hh, ll);
        *reinterpret_cast<uint32_t*>(&g_ctxh[r0]) = hh;
        *reinterpret_cast<uint32_t*>(&g_ctxl[r0]) = ll;
        split2_u32(o[nt][2] * i1, o[nt][3] * i1, hh, ll);
        *reinterpret_cast<uint32_t*>(&g_ctxh[r1]) = hh;
        *reinterpret_cast<uint32_t*>(&g_ctxl[r1]) = ll;
    }
}

// ---------------- launch -------------------------------------------------------
extern "C" void kernel_launch(void* const* d_in, const int* in_sizes, int n_in,
                              void* d_out, int out_size)
{
    const float* act[3] = {0, 0, 0};
    const float* wgt[4] = {0, 0, 0, 0};
    const float* bia[4] = {0, 0, 0, 0};
    int na = 0, nw = 0, nb = 0;
    for (int i = 0; i < n_in; i++) {
        const int s = in_sizes[i];
        if (s == NTOK * DM)      { if (na < 3) act[na++] = (const float*)d_in[i]; }
        else if (s == DM * DM)   { if (nw < 4) wgt[nw++] = (const float*)d_in[i]; }
        else if (s == DM)        { if (nb < 4) bia[nb++] = (const float*)d_in[i]; }
    }
    const float* query = act[0];
    const float* key   = act[1];
    const float* value = act[2];
    const float* Wq = wgt[0]; const float* Wk = wgt[1];
    const float* Wv = wgt[2]; const float* Wo = wgt[3];
    const float* bq = bia[0]; const float* bk = bia[1];
    const float* bv = bia[2]; const float* bo = bia[3];
    float* out = (float*)d_out;

    split_w_all<<<dim3(DM * DM / 4 / 256, 4), 256>>>(Wq, Wk, Wv, Wo);
    split_act<<<dim3(NTOK * DM / 4 / 256, 3), 256>>>(query, key, value);

    cudaFuncSetAttribute(gemm_mma, cudaFuncAttributeMaxDynamicSharedMemorySize, GSMEM);

    // fused QKV projections (V writes pre-split bf16)
    gemm_mma<<<dim3(DM / 128, NTOK / 128, 3), 256, GSMEM>>>(bq, bk, bv, out, 0);

    // RoPE + split on q, k
    rope_split<<<NTOK, 512>>>();

    // mma flash attention (pure bf16 inputs) -> g_ctxh/g_ctxl
    attn_mma<<<dim3(SEQ / 64, NH, BATCH), 128>>>();

    // output projection: ctx @ Wo^T + bo -> out
    gemm_mma<<<dim3(DM / 128, NTOK / 128, 1), 256, GSMEM>>>(bo, bo, bo, out, 1);
}

// round 14
// speedup vs baseline: 1.1163x; 1.1163x over previous
#include <cuda_runtime.h>
#include <cuda_bf16.h>
#include <stdint.h>
#include <math.h>

// Problem constants
#define BATCH 16
#define SEQ 512
#define DM 1024
#define NH 16
#define HD 64
#define NTOK (BATCH * SEQ)   // 8192

// ---------------- scratch (allocation-free: __device__ globals) ----------------
__device__ float g_q[NTOK * DM];          // fp32 Q proj (rope input)
__device__ float g_k[NTOK * DM];          // fp32 K proj (rope input)
__device__ __nv_bfloat16 g_wh[4u * DM * DM];
__device__ __nv_bfloat16 g_wl[4u * DM * DM];
__device__ __nv_bfloat16 g_ah[3u * NTOK * DM];
__device__ __nv_bfloat16 g_al[3u * NTOK * DM];
__device__ __nv_bfloat16 g_qh[NTOK * DM];
__device__ __nv_bfloat16 g_ql[NTOK * DM];
__device__ __nv_bfloat16 g_kh[NTOK * DM];
__device__ __nv_bfloat16 g_kl[NTOK * DM];
__device__ __nv_bfloat16 g_vh[NTOK * DM];
__device__ __nv_bfloat16 g_vl[NTOK * DM];
__device__ __nv_bfloat16 g_ctxh[NTOK * DM];
__device__ __nv_bfloat16 g_ctxl[NTOK * DM];

// ---------------- warp-level tensor core primitives ----------------------------
__device__ __forceinline__ uint32_t smem_u32(const void* p) {
    uint32_t a;
    asm("{ .reg .u64 t; cvta.to.shared.u64 t, %1; cvt.u32.u64 %0, t; }"
        : "=r"(a) : "l"(p));
    return a;
}
__device__ __forceinline__ void ldm_x4(uint32_t* r, uint32_t addr) {
    asm volatile("ldmatrix.sync.aligned.m8n8.x4.shared.b16 {%0,%1,%2,%3}, [%4];"
        : "=r"(r[0]), "=r"(r[1]), "=r"(r[2]), "=r"(r[3]) : "r"(addr));
}
__device__ __forceinline__ void ldm_x2(uint32_t* r, uint32_t addr) {
    asm volatile("ldmatrix.sync.aligned.m8n8.x2.shared.b16 {%0,%1}, [%2];"
        : "=r"(r[0]), "=r"(r[1]) : "r"(addr));
}
__device__ __forceinline__ void ldm_x2t(uint32_t* r, uint32_t addr) {
    asm volatile("ldmatrix.sync.aligned.m8n8.x2.trans.shared.b16 {%0,%1}, [%2];"
        : "=r"(r[0]), "=r"(r[1]) : "r"(addr));
}
__device__ __forceinline__ void mma_bf16(float* d, const uint32_t* a, const uint32_t* b) {
    asm volatile("mma.sync.aligned.m16n8k16.row.col.f32.bf16.bf16.f32 "
        "{%0,%1,%2,%3}, {%4,%5,%6,%7}, {%8,%9}, {%0,%1,%2,%3};"
        : "+f"(d[0]), "+f"(d[1]), "+f"(d[2]), "+f"(d[3])
        : "r"(a[0]), "r"(a[1]), "r"(a[2]), "r"(a[3]), "r"(b[0]), "r"(b[1]));
}
__device__ __forceinline__ void cp16(uint32_t dst, const void* src) {
    asm volatile("cp.async.cg.shared.global [%0], [%1], 16;" :: "r"(dst), "l"(src));
}
#define CP_COMMIT() asm volatile("cp.async.commit_group;" ::: "memory")
template <int N> __device__ __forceinline__ void cp_wait() {
    asm volatile("cp.async.wait_group %0;" :: "n"(N) : "memory");
}

// fast exp on the FMA/ALU pipes (no MUFU). |rel err| < 3e-6 for x <= 0.
__device__ __forceinline__ float fexp(float x) {
    float t = fmaxf(x * 1.4426950408889634f, -125.0f);
    const float magic = 12582912.0f;
    float z = t + magic;
    int   n = __float_as_int(z) - 0x4B400000;
    float f = t - (z - magic);
    float p = 0.00133336f;
    p = fmaf(p, f, 0.00961813f);
    p = fmaf(p, f, 0.05550411f);
    p = fmaf(p, f, 0.24022651f);
    p = fmaf(p, f, 0.69314718f);
    p = fmaf(p, f, 1.0f);
    return p * __int_as_float((n + 127) << 23);
}

// split helpers: hi = truncate-to-bf16(x), lo = truncate-to-bf16(x - hi)
__device__ __forceinline__ void split2_u32(float a, float b, uint32_t& hi, uint32_t& lo) {
    const uint32_t ua = __float_as_uint(a), ub = __float_as_uint(b);
    const uint32_t ra = __float_as_uint(a - __uint_as_float(ua & 0xFFFF0000u));
    const uint32_t rb = __float_as_uint(b - __uint_as_float(ub & 0xFFFF0000u));
    hi = __byte_perm(ua, ub, 0x7632);
    lo = __byte_perm(ra, rb, 0x7632);
}

// ---------------- pre-split kernels: fp32 -> bf16 hi/lo ------------------------
__device__ __forceinline__ void split4_store(
    const float* __restrict__ src, __nv_bfloat16* dh, __nv_bfloat16* dl, size_t i)
{
    const float4 v = *reinterpret_cast<const float4*>(src + i);
    uint32_t h0, l0, h1, l1;
    split2_u32(v.x, v.y, h0, l0);
    split2_u32(v.z, v.w, h1, l1);
    uint2 hi, lo;
    hi.x = h0; hi.y = h1; lo.x = l0; lo.y = l1;
    *reinterpret_cast<uint2*>(dh + i) = hi;
    *reinterpret_cast<uint2*>(dl + i) = lo;
}

__global__ __launch_bounds__(256) void split_w_all(
    const float* __restrict__ W0, const float* __restrict__ W1,
    const float* __restrict__ W2, const float* __restrict__ W3)
{
    const float* W = (blockIdx.y == 0) ? W0
                   : (blockIdx.y == 1) ? W1
                   : (blockIdx.y == 2) ? W2 : W3;
    const size_t d0 = (size_t)blockIdx.y * DM * DM;
    const size_t i = ((size_t)blockIdx.x * 256 + threadIdx.x) * 4;
    split4_store(W, g_wh + d0, g_wl + d0, i);
}

__global__ __launch_bounds__(256) void split_act(
    const float* __restrict__ A0, const float* __restrict__ A1,
    const float* __restrict__ A2)
{
    const float* A = (blockIdx.y == 0) ? A0
                   : (blockIdx.y == 1) ? A1 : A2;
    const size_t d0 = (size_t)blockIdx.y * NTOK * DM;
    const size_t i = ((size_t)blockIdx.x * 256 + threadIdx.x) * 4;
    split4_store(A, g_ah + d0, g_al + d0, i);
}

// ================== 2-stage cp.async mma.sync GEMM (proven R11 config) =========
// 2 CTA/SM, per-kk fragment loads, 3 passes of 16 independent MMAs.
#define GST 40
#define SSB (128 * GST * 2)   // 10240 B per array per stage
#define GSMEM (8 * SSB)       // 81920 B

// mode 0: fused QKV (blockIdx.z = sel 0..2); mode 1: O projection (sel 3)
__global__ __launch_bounds__(256, 2) void gemm_mma(
    const float* __restrict__ b0, const float* __restrict__ b1,
    const float* __restrict__ b2, float* Cout, int mode)
{
    const int sel = (mode == 0) ? (int)blockIdx.z : 3;
    const __nv_bfloat16* ah = (sel < 3) ? g_ah + (size_t)sel * NTOK * DM : g_ctxh;
    const __nv_bfloat16* al = (sel < 3) ? g_al + (size_t)sel * NTOK * DM : g_ctxl;
    const __nv_bfloat16* wh = g_wh + (size_t)sel * DM * DM;
    const __nv_bfloat16* wl = g_wl + (size_t)sel * DM * DM;
    const float* bias = (sel == 0) ? b0 : (sel == 1) ? b1 : (sel == 2) ? b2 : b0;

    extern __shared__ __align__(16) __nv_bfloat16 smg[];
    const uint32_t smB = smem_u32(smg);

    const int tid = threadIdx.x;
    const int lane = tid & 31;
    const int wid = tid >> 5;
    const int wm = wid & 1;
    const int wn = wid >> 1;
    const int bm = blockIdx.y * 128;
    const int bn = blockIdx.x * 128;

    const int grow = tid >> 1;
    const int gcol = (tid & 1) * 16;
    const uint32_t rcB = (uint32_t)(grow * GST + gcol) * 2;
    const size_t aRow = (size_t)(bm + grow) * DM + gcol;
    const size_t bRow = (size_t)(bn + grow) * DM + gcol;

    const int la = lane & 15;
    const uint32_t aRowOff = (uint32_t)((wm * 64 + la) * GST + (lane >> 4) * 8) * 2;
    const uint32_t bRowOff = (uint32_t)((wn * 32 + (la & 7)) * GST + ((la >> 3) & 1) * 8) * 2;

    float acc[4][4][4];
    #pragma unroll
    for (int mt = 0; mt < 4; mt++)
        #pragma unroll
        for (int nt = 0; nt < 4; nt++)
            #pragma unroll
            for (int e = 0; e < 4; e++) acc[mt][nt][e] = 0.f;

    {
        const uint32_t d = smB + rcB;
        cp16(d,               ah + aRow); cp16(d + 16,           ah + aRow + 8);
        cp16(d + 2 * SSB,     al + aRow); cp16(d + 2 * SSB + 16, al + aRow + 8);
        cp16(d + 4 * SSB,     wh + bRow); cp16(d + 4 * SSB + 16, wh + bRow + 8);
        cp16(d + 6 * SSB,     wl + bRow); cp16(d + 6 * SSB + 16, wl + bRow + 8);
        CP_COMMIT();
    }

    #pragma unroll 1
    for (int it = 0; it < DM / 32; it++) {
        if (it + 1 < DM / 32) {
            const uint32_t d = smB + ((it + 1) & 1) * SSB + rcB;
            const size_t ao = aRow + (it + 1) * 32;
            const size_t bo = bRow + (it + 1) * 32;
            cp16(d,               ah + ao); cp16(d + 16,           ah + ao + 8);
            cp16(d + 2 * SSB,     al + ao); cp16(d + 2 * SSB + 16, al + ao + 8);
            cp16(d + 4 * SSB,     wh + bo); cp16(d + 4 * SSB + 16, wh + bo + 8);
            cp16(d + 6 * SSB,     wl + bo); cp16(d + 6 * SSB + 16, wl + bo + 8);
            CP_COMMIT();
            cp_wait<1>();
        } else {
            cp_wait<0>();
        }
        __syncthreads();

        const uint32_t sb = (uint32_t)((it & 1) * SSB);
        const uint32_t aHiB = smB + sb;
        const uint32_t aLoB = smB + 2 * SSB + sb;
        const uint32_t bHiB = smB + 4 * SSB + sb;
        const uint32_t bLoB = smB + 6 * SSB + sb;

        #pragma unroll
        for (int kk = 0; kk < 2; kk++) {
            const uint32_t kOff = (uint32_t)(kk * 16) * 2;
            uint32_t ahf[4][4], alf[4][4], bhf[4][2], blf[4][2];
            #pragma unroll
            for (int mt = 0; mt < 4; mt++) {
                const uint32_t ro = aRowOff + (uint32_t)(mt * 16 * GST) * 2 + kOff;
                ldm_x4(ahf[mt], aHiB + ro);
                ldm_x4(alf[mt], aLoB + ro);
            }
            #pragma unroll
            for (int nt = 0; nt < 4; nt++) {
                const uint32_t ro = bRowOff + (uint32_t)(nt * 8 * GST) * 2 + kOff;
                ldm_x2(bhf[nt], bHiB + ro);
                ldm_x2(blf[nt], bLoB + ro);
            }
            // 3 passes of 16 independent MMAs
            #pragma unroll
            for (int mt = 0; mt < 4; mt++)
                #pragma unroll
                for (int nt = 0; nt < 4; nt++)
                    mma_bf16(acc[mt][nt], ahf[mt], bhf[nt]);
            #pragma unroll
            for (int mt = 0; mt < 4; mt++)
                #pragma unroll
                for (int nt = 0; nt < 4; nt++)
                    mma_bf16(acc[mt][nt], ahf[mt], blf[nt]);
            #pragma unroll
            for (int mt = 0; mt < 4; mt++)
                #pragma unroll
                for (int nt = 0; nt < 4; nt++)
                    mma_bf16(acc[mt][nt], alf[mt], bhf[nt]);
        }
        __syncthreads();
    }

    const int er = lane >> 2;
    const int ec = (lane & 3) * 2;
    if (sel == 2) {
        // V projection: write pre-split bf16 hi/lo (post-loop; regs reuse frags)
        #pragma unroll
        for (int mt = 0; mt < 4; mt++) {
            #pragma unroll
            for (int nt = 0; nt < 4; nt++) {
                const int col = bn + wn * 32 + nt * 8 + ec;
                const float c0 = bias[col], c1 = bias[col + 1];
                const int r0 = bm + wm * 64 + mt * 16 + er;
                uint32_t h, l;
                split2_u32(acc[mt][nt][0] + c0, acc[mt][nt][1] + c1, h, l);
                *reinterpret_cast<uint32_t*>(&g_vh[(size_t)r0 * DM + col]) = h;
                *reinterpret_cast<uint32_t*>(&g_vl[(size_t)r0 * DM + col]) = l;
                split2_u32(acc[mt][nt][2] + c0, acc[mt][nt][3] + c1, h, l);
                *reinterpret_cast<uint32_t*>(&g_vh[(size_t)(r0 + 8) * DM + col]) = h;
                *reinterpret_cast<uint32_t*>(&g_vl[(size_t)(r0 + 8) * DM + col]) = l;
            }
        }
    } else {
        float* C = (sel == 0) ? g_q : (sel == 1) ? g_k : Cout;
        #pragma unroll
        for (int mt = 0; mt < 4; mt++) {
            #pragma unroll
            for (int nt = 0; nt < 4; nt++) {
                const int col = bn + wn * 32 + nt * 8 + ec;
                const float c0 = bias[col], c1 = bias[col + 1];
                const int r0 = bm + wm * 64 + mt * 16 + er;
                float2 v0, v1;
                v0.x = acc[mt][nt][0] + c0; v0.y = acc[mt][nt][1] + c1;
                v1.x = acc[mt][nt][2] + c0; v1.y = acc[mt][nt][3] + c1;
                *reinterpret_cast<float2*>(&C[(size_t)r0 * DM + col]) = v0;
                *reinterpret_cast<float2*>(&C[(size_t)(r0 + 8) * DM + col]) = v1;
            }
        }
    }
}

// ---------------- RoPE + split: fp32 q,k -> roped bf16 hi/lo -------------------
__global__ __launch_bounds__(512) void rope_split()
{
    const int token = blockIdx.x;
    const int pos = token & (SEQ - 1);
    const int h = threadIdx.x >> 5;
    const int i = threadIdx.x & 31;

    const float expo = (float)(2 * i) / 64.0f;
    const float invf = 1.0f / powf(10000.0f, expo);
    const float ang = (float)pos * invf;
    const float c = cosf(ang);
    const float s = sinf(ang);

    const size_t base = (size_t)token * DM + h * HD;
    {
        const float a = g_q[base + i], b = g_q[base + i + 32];
        const float r1 = 0.125f * (a * c - b * s);
        const float r2 = 0.125f * (b * c + a * s);
        const uint32_t u1 = __float_as_uint(r1), u2 = __float_as_uint(r2);
        g_qh[base + i]      = __ushort_as_bfloat16((unsigned short)(u1 >> 16));
        g_qh[base + i + 32] = __ushort_as_bfloat16((unsigned short)(u2 >> 16));
        const float l1 = r1 - __uint_as_float(u1 & 0xFFFF0000u);
        const float l2 = r2 - __uint_as_float(u2 & 0xFFFF0000u);
        g_ql[base + i]      = __ushort_as_bfloat16((unsigned short)(__float_as_uint(l1) >> 16));
        g_ql[base + i + 32] = __ushort_as_bfloat16((unsigned short)(__float_as_uint(l2) >> 16));
    }
    {
        const float a = g_k[base + i], b = g_k[base + i + 32];
        const float r1 = a * c - b * s;
        const float r2 = b * c + a * s;
        const uint32_t u1 = __float_as_uint(r1), u2 = __float_as_uint(r2);
        g_kh[base + i]      = __ushort_as_bfloat16((unsigned short)(u1 >> 16));
        g_kh[base + i + 32] = __ushort_as_bfloat16((unsigned short)(u2 >> 16));
        const float l1 = r1 - __uint_as_float(u1 & 0xFFFF0000u);
        const float l2 = r2 - __uint_as_float(u2 & 0xFFFF0000u);
        g_kl[base + i]      = __ushort_as_bfloat16((unsigned short)(__float_as_uint(l1) >> 16));
        g_kl[base + i + 32] = __ushort_as_bfloat16((unsigned short)(__float_as_uint(l2) >> 16));
    }
}

// ================== mma.sync flash attention (bf16 cp.async inputs) ============
#define AST 72

__global__ __launch_bounds__(128) void attn_mma()
{
    __shared__ __align__(16) __nv_bfloat16 sKh[64 * AST];
    __shared__ __align__(16) __nv_bfloat16 sKl[64 * AST];
    __shared__ __align__(16) __nv_bfloat16 sVh[64 * AST];
    __shared__ __align__(16) __nv_bfloat16 sVl[64 * AST];

    const int tid = threadIdx.x;
    const int lane = tid & 31;
    const int w = tid >> 5;
    const int q0 = blockIdx.x * 64;
    const int h  = blockIdx.y;
    const int b  = blockIdx.z;

    const uint32_t kHiB = smem_u32(sKh), kLoB = smem_u32(sKl);
    const uint32_t vHiB = smem_u32(sVh), vLoB = smem_u32(sVl);

    // loader mapping: row = tid>>1, 32-elem half = tid&1; 4 cp16 per array
    const int lrow = tid >> 1;
    const int lhalf = tid & 1;
    const uint32_t sOff = (uint32_t)(lrow * AST + lhalf * 32) * 2;
    const size_t gColBase = (size_t)h * HD + lhalf * 32;

    // ---- stage Q (pre-roped, pre-scaled, pre-split) ----
    {
        const size_t src = (size_t)(b * SEQ + q0 + lrow) * DM + gColBase;
        #pragma unroll
        for (int cix = 0; cix < 4; cix++) {
            cp16(kHiB + sOff + cix * 16, g_qh + src + cix * 8);
            cp16(kLoB + sOff + cix * 16, g_ql + src + cix * 8);
        }
        CP_COMMIT();
        cp_wait<0>();
    }
    __syncthreads();

    uint32_t qh[4][4], ql[4][4];
    {
        const uint32_t ro0 = (uint32_t)((w * 16 + (lane & 15)) * AST + (lane >> 4) * 8) * 2;
        #pragma unroll
        for (int kc = 0; kc < 4; kc++) {
            ldm_x4(qh[kc], kHiB + ro0 + (uint32_t)(kc * 16) * 2);
            ldm_x4(ql[kc], kLoB + ro0 + (uint32_t)(kc * 16) * 2);
        }
    }
    __syncthreads();

    float o[8][4];
    #pragma unroll
    for (int nt = 0; nt < 8; nt++)
        #pragma unroll
        for (int e = 0; e < 4; e++) o[nt][e] = 0.f;
    float m0 = -3.0e38f, m1 = -3.0e38f, l0 = 0.f, l1 = 0.f;

    const uint32_t bro = (uint32_t)((lane & 7) * AST + ((lane >> 3) & 1) * 8) * 2;
    const uint32_t vro = (uint32_t)(((lane & 7) + 8 * ((lane >> 3) & 1)) * AST) * 2;

    #pragma unroll 1
    for (int kt = 0; kt < SEQ / 64; kt++) {
        // ---- load K/V tiles (pre-split bf16, cp.async; 4 cp16 per array) ----
        {
            const size_t src = (size_t)(b * SEQ + kt * 64 + lrow) * DM + gColBase;
            #pragma unroll
            for (int cix = 0; cix < 4; cix++) {
                cp16(kHiB + sOff + cix * 16, g_kh + src + cix * 8);
                cp16(kLoB + sOff + cix * 16, g_kl + src + cix * 8);
                cp16(vHiB + sOff + cix * 16, g_vh + src + cix * 8);
                cp16(vLoB + sOff + cix * 16, g_vl + src + cix * 8);
            }
            CP_COMMIT();
            cp_wait<0>();
        }
        __syncthreads();

        float s[8][4];
        #pragma unroll
        for (int nt = 0; nt < 8; nt++)
            #pragma unroll
            for (int e = 0; e < 4; e++) s[nt][e] = 0.f;

        #pragma unroll
        for (int kc = 0; kc < 4; kc++) {
            const uint32_t kOff = (uint32_t)(kc * 16) * 2;
            #pragma unroll
            for (int nt = 0; nt < 8; nt++) {
                const uint32_t ro = bro + (uint32_t)(nt * 8 * AST) * 2 + kOff;
                uint32_t bh[2], bl[2];
                ldm_x2(bh, kHiB + ro);
                ldm_x2(bl, kLoB + ro);
                mma_bf16(s[nt], qh[kc], bh);
                mma_bf16(s[nt], qh[kc], bl);
                mma_bf16(s[nt], ql[kc], bh);
            }
        }

        float tm0 = -3.0e38f, tm1 = -3.0e38f;
        #pragma unroll
        for (int nt = 0; nt < 8; nt++) {
            tm0 = fmaxf(tm0, fmaxf(s[nt][0], s[nt][1]));
            tm1 = fmaxf(tm1, fmaxf(s[nt][2], s[nt][3]));
        }
        #pragma unroll
        for (int off = 1; off < 4; off <<= 1) {
            tm0 = fmaxf(tm0, __shfl_xor_sync(0xffffffffu, tm0, off));
            tm1 = fmaxf(tm1, __shfl_xor_sync(0xffffffffu, tm1, off));
        }
        const float nm0 = fmaxf(m0, tm0), nm1 = fmaxf(m1, tm1);
        const float corr0 = fexp(m0 - nm0), corr1 = fexp(m1 - nm1);
        float rs0 = 0.f, rs1 = 0.f;
        #pragma unroll
        for (int nt = 0; nt < 8; nt++) {
            s[nt][0] = fexp(s[nt][0] - nm0);
            s[nt][1] = fexp(s[nt][1] - nm0);
            s[nt][2] = fexp(s[nt][2] - nm1);
            s[nt][3] = fexp(s[nt][3] - nm1);
            rs0 += s[nt][0] + s[nt][1];
            rs1 += s[nt][2] + s[nt][3];
        }
        #pragma unroll
        for (int off = 1; off < 4; off <<= 1) {
            rs0 += __shfl_xor_sync(0xffffffffu, rs0, off);
            rs1 += __shfl_xor_sync(0xffffffffu, rs1, off);
        }
        l0 = l0 * corr0 + rs0;  m0 = nm0;
        l1 = l1 * corr1 + rs1;  m1 = nm1;
        #pragma unroll
        for (int nt = 0; nt < 8; nt++) {
            o[nt][0] *= corr0; o[nt][1] *= corr0;
            o[nt][2] *= corr1; o[nt][3] *= corr1;
        }

        uint32_t ph[4][4], pl[4][4];
        #pragma unroll
        for (int j = 0; j < 4; j++) {
            const int ta = 2 * j, tb = 2 * j + 1;
            split2_u32(s[ta][0], s[ta][1], ph[j][0], pl[j][0]);
            split2_u32(s[ta][2], s[ta][3], ph[j][1], pl[j][1]);
            split2_u32(s[tb][0], s[tb][1], ph[j][2], pl[j][2]);
            split2_u32(s[tb][2], s[tb][3], ph[j][3], pl[j][3]);
        }

        #pragma unroll
        for (int j = 0; j < 4; j++) {
            const uint32_t jOff = (uint32_t)(j * 16 * AST) * 2;
            #pragma unroll
            for (int nt = 0; nt < 8; nt++) {
                const uint32_t ro = vro + jOff + (uint32_t)(nt * 8) * 2;
                uint32_t bh[2], bl[2];
                ldm_x2t(bh, vHiB + ro);
                ldm_x2t(bl, vLoB + ro);
                mma_bf16(o[nt], ph[j], bh);
                mma_bf16(o[nt], ph[j], bl);
                mma_bf16(o[nt], pl[j], bh);
            }
        }
        __syncthreads();
    }

    const float i0 = 1.0f / l0, i1 = 1.0f / l1;
    const int er = lane >> 2;
    const int ec = (lane & 3) * 2;
    #pragma unroll
    for (int nt = 0; nt < 8; nt++) {
        const int col = h * HD + nt * 8 + ec;
        const size_t r0 = (size_t)(b * SEQ + q0 + w * 16 + er) * DM + col;
        const size_t r1 = r0 + 8 * DM;
        uint32_t hh, ll;
        split2_u32(o[nt][0] * i0, o[nt][1] * i0, hh, ll);
        *reinterpret_cast<uint32_t*>(&g_ctxh[r0]) = hh;
        *reinterpret_cast<uint32_t*>(&g_ctxl[r0]) = ll;
        split2_u32(o[nt][2] * i1, o[nt][3] * i1, hh, ll);
        *reinterpret_cast<uint32_t*>(&g_ctxh[r1]) = hh;
        *reinterpret_cast<uint32_t*>(&g_ctxl[r1]) = ll;
    }
}

// ---------------- launch -------------------------------------------------------
extern "C" void kernel_launch(void* const* d_in, const int* in_sizes, int n_in,
                              void* d_out, int out_size)
{
    const float* act[3] = {0, 0, 0};
    const float* wgt[4] = {0, 0, 0, 0};
    const float* bia[4] = {0, 0, 0, 0};
    int na = 0, nw = 0, nb = 0;
    for (int i = 0; i < n_in; i++) {
        const int s = in_sizes[i];
        if (s == NTOK * DM)      { if (na < 3) act[na++] = (const float*)d_in[i]; }
        else if (s == DM * DM)   { if (nw < 4) wgt[nw++] = (const float*)d_in[i]; }
        else if (s == DM)        { if (nb < 4) bia[nb++] = (const float*)d_in[i]; }
    }
    const float* query = act[0];
    const float* key   = act[1];
    const float* value = act[2];
    const float* Wq = wgt[0]; const float* Wk = wgt[1];
    const float* Wv = wgt[2]; const float* Wo = wgt[3];
    const float* bq = bia[0]; const float* bk = bia[1];
    const float* bv = bia[2]; const float* bo = bia[3];
    float* out = (float*)d_out;

    split_w_all<<<dim3(DM * DM / 4 / 256, 4), 256>>>(Wq, Wk, Wv, Wo);
    split_act<<<dim3(NTOK * DM / 4 / 256, 3), 256>>>(query, key, value);

    cudaFuncSetAttribute(gemm_mma, cudaFuncAttributeMaxDynamicSharedMemorySize, GSMEM);

    // fused QKV projections (V writes pre-split bf16)
    gemm_mma<<<dim3(DM / 128, NTOK / 128, 3), 256, GSMEM>>>(bq, bk, bv, out, 0);

    // RoPE + split on q, k
    rope_split<<<NTOK, 512>>>();

    // mma flash attention (pure bf16 inputs) -> g_ctxh/g_ctxl
    attn_mma<<<dim3(SEQ / 64, NH, BATCH), 128>>>();

    // output projection: ctx @ Wo^T + bo -> out
    gemm_mma<<<dim3(DM / 128, NTOK / 128, 1), 256, GSMEM>>>(bo, bo, bo, out, 1);
}